// round 8
// baseline (speedup 1.0000x reference)
#include <cuda_runtime.h>
#include <cstdint>

// Problem dims
#define BB 16          // batch
#define TT 256         // timesteps
#define NB 32          // LSTM blocks
#define II 64          // input per block
#define HH 128         // hidden per block
#define G4 512         // 4*H gate rows per block

// ---------------------------------------------------------------------------
// Scratch (device globals: allocation-free per harness rules)
// ---------------------------------------------------------------------------
// gates_x[t][n][b][g]  (biases folded in):  256*32*16*512 floats = 268 MB
__device__ float g_gx[(size_t)TT * NB * BB * G4];
// transposed W_hh: [n][kc][g][4] with kc = k/4 (32 chunks): 32*32*512*4 = 8 MB
__device__ float g_wt4[(size_t)NB * (HH / 4) * G4 * 4];

// ---------------------------------------------------------------------------
// Kernel 0: transpose W_hh [n][g][k] -> [n][k/4][g][4] (float4 per (g, kc))
// ---------------------------------------------------------------------------
__global__ void k_transpose(const float* __restrict__ whh) {
    int idx = blockIdx.x * blockDim.x + threadIdx.x;   // over NB*32*512
    int g  = idx & 511;
    int kc = (idx >> 9) & 31;
    int n  = idx >> 14;
    float4 v = *(const float4*)(whh + ((size_t)(n * G4 + g)) * HH + kc * 4);
    *(float4*)(g_wt4 + ((size_t)((n * 32 + kc) * G4 + g)) * 4) = v;
}

// ---------------------------------------------------------------------------
// Kernel A: gates_x[b,t,n,g] = sum_i x[b,t,n*64+i] * W_ih[n,g,i] + bi + bh
// Grid: 512 CTAs = (n in [0,32)) x (tc in [0,16)); 512 threads, thread = g.
// ---------------------------------------------------------------------------
__global__ void __launch_bounds__(512, 1)
k_gatesx(const float* __restrict__ x,
         const float* __restrict__ wih,
         const float* __restrict__ bih,
         const float* __restrict__ bhh) {
    extern __shared__ float xs[];           // [256 rows][64] = 64 KB
    int n  = blockIdx.x & 31;
    int tc = blockIdx.x >> 5;               // 0..15 (16 timesteps each)
    int g  = threadIdx.x;

    // Register-resident weight row for this gate (64 floats = 16 float4)
    float4 w[16];
    const float4* wp = (const float4*)(wih + ((size_t)(n * G4 + g)) * II);
#pragma unroll
    for (int j = 0; j < 16; j++) w[j] = wp[j];
    float bias = bih[n * G4 + g] + bhh[n * G4 + g];

    // Stage 256 x-rows (16 t x 16 b), row r = b*16 + tl
    for (int idx = threadIdx.x; idx < 256 * 16; idx += 512) {
        int r  = idx >> 4;
        int i4 = idx & 15;
        int b  = r >> 4;
        int tl = r & 15;
        int t  = tc * 16 + tl;
        ((float4*)xs)[idx] =
            *(const float4*)(x + (size_t)(b * TT + t) * (NB * II) + n * II + i4 * 4);
    }
    __syncthreads();

    for (int r = 0; r < 256; r++) {
        const float4* xr = ((const float4*)xs) + r * 16;
        float acc = bias;
#pragma unroll
        for (int j = 0; j < 16; j++) {
            float4 xv = xr[j];
            acc += w[j].x * xv.x;
            acc += w[j].y * xv.y;
            acc += w[j].z * xv.z;
            acc += w[j].w * xv.w;
        }
        int b  = r >> 4;
        int tl = r & 15;
        int t  = tc * 16 + tl;
        g_gx[((size_t)(t * NB + n) * BB + b) * G4 + g] = acc;
    }
}

// ---------------------------------------------------------------------------
// Kernel B: recurrence. Grid: 128 CTAs = (n x 4 batch-groups of 4 batches).
// 512 threads. Gemv phase: thread = gate row g (512). Epilogue: thread ->
// (local batch eb = tid>>7, hidden eh = tid&127). No inter-CTA sync.
// SMEM: ws4 (kc 0..15 weight cache, 128 KB) | h (4x128) | gates (4x512).
// ---------------------------------------------------------------------------
__global__ void __launch_bounds__(512, 1)
k_recur(const float* __restrict__ h0,
        const float* __restrict__ c0,
        float* __restrict__ out) {
    extern __shared__ float smem[];
    float4* ws4 = (float4*)smem;                 // [16][512] float4
    float*  hs  = smem + 16 * 512 * 4;           // [4][128] floats
    float*  gs  = hs + 4 * HH;                   // [4][512] floats

    int n  = blockIdx.x >> 2;
    int bg = blockIdx.x & 3;
    int b0 = bg * 4;
    int tid = threadIdx.x;

    // Load SMEM-cached half of the transposed weights (kc 0..15)
    const float4* wglob = (const float4*)(g_wt4 + (size_t)n * 32 * G4 * 4);
    for (int idx = tid; idx < 16 * 512; idx += 512) ws4[idx] = wglob[idx];

    // Initial state: h into SMEM, c into epilogue-thread register
    int eb = tid >> 7;       // local batch 0..3
    int eh = tid & 127;      // hidden index
    float c_reg = c0[(b0 + eb) * (NB * HH) + n * HH + eh];
    hs[eb * HH + eh] = h0[(b0 + eb) * (NB * HH) + n * HH + eh];
    __syncthreads();

    int g = tid;
    const float4* wstream = wglob + 16 * 512;    // kc 16..31 streamed from L2

    for (int t = 0; t < TT; t++) {
        // gates_x for this step (issued early; consumed after the gemv)
        const float* gxp = g_gx + ((size_t)(t * NB + n) * BB + b0) * G4 + g;
        float gx0 = gxp[0];
        float gx1 = gxp[512];
        float gx2 = gxp[1024];
        float gx3 = gxp[1536];

        float a0 = 0.f, a1 = 0.f, a2 = 0.f, a3 = 0.f;
        const float4* h4 = (const float4*)hs;    // [b*32 + kc]

#pragma unroll
        for (int kc = 0; kc < 16; kc++) {
            float4 w = ws4[kc * 512 + g];
            float4 hv;
            hv = h4[kc];
            a0 += w.x * hv.x; a0 += w.y * hv.y; a0 += w.z * hv.z; a0 += w.w * hv.w;
            hv = h4[32 + kc];
            a1 += w.x * hv.x; a1 += w.y * hv.y; a1 += w.z * hv.z; a1 += w.w * hv.w;
            hv = h4[64 + kc];
            a2 += w.x * hv.x; a2 += w.y * hv.y; a2 += w.z * hv.z; a2 += w.w * hv.w;
            hv = h4[96 + kc];
            a3 += w.x * hv.x; a3 += w.y * hv.y; a3 += w.z * hv.z; a3 += w.w * hv.w;
        }
#pragma unroll
        for (int kc = 0; kc < 16; kc++) {
            float4 w = wstream[kc * 512 + g];    // L2-resident, shared by 4 CTAs
            float4 hv;
            hv = h4[16 + kc];
            a0 += w.x * hv.x; a0 += w.y * hv.y; a0 += w.z * hv.z; a0 += w.w * hv.w;
            hv = h4[48 + kc];
            a1 += w.x * hv.x; a1 += w.y * hv.y; a1 += w.z * hv.z; a1 += w.w * hv.w;
            hv = h4[80 + kc];
            a2 += w.x * hv.x; a2 += w.y * hv.y; a2 += w.z * hv.z; a2 += w.w * hv.w;
            hv = h4[112 + kc];
            a3 += w.x * hv.x; a3 += w.y * hv.y; a3 += w.z * hv.z; a3 += w.w * hv.w;
        }

        gs[0 * 512 + g] = a0 + gx0;
        gs[1 * 512 + g] = a1 + gx1;
        gs[2 * 512 + g] = a2 + gx2;
        gs[3 * 512 + g] = a3 + gx3;
        __syncthreads();

        // Epilogue: gate activations + state update
        float gi = gs[eb * 512 + eh];
        float gf = gs[eb * 512 + 128 + eh];
        float gg = gs[eb * 512 + 256 + eh];
        float go = gs[eb * 512 + 384 + eh];

        float ig = 1.f / (1.f + __expf(-gi));
        float fg = 1.f / (1.f + __expf(-gf));
        float gt = 1.f - __fdividef(2.f, __expf(2.f * gg) + 1.f);
        float og = 1.f / (1.f + __expf(-go));

        c_reg = fg * c_reg + ig * gt;
        float ct = 1.f - __fdividef(2.f, __expf(2.f * c_reg) + 1.f);
        float hn = og * ct;

        hs[eb * HH + eh] = hn;
        out[((size_t)(b0 + eb) * TT + t) * (NB * HH) + n * HH + eh] = hn;
        __syncthreads();
    }

    // Final states: h_n then c_n appended after the [B,T,N*H] output
    size_t base = (size_t)BB * TT * NB * HH;
    out[base + (b0 + eb) * (NB * HH) + n * HH + eh] = hs[eb * HH + eh];
    out[base + (size_t)BB * NB * HH + (b0 + eb) * (NB * HH) + n * HH + eh] = c_reg;
}

// ---------------------------------------------------------------------------
// Launch
// ---------------------------------------------------------------------------
extern "C" void kernel_launch(void* const* d_in, const int* in_sizes, int n_in,
                              void* d_out, int out_size) {
    const float* x   = (const float*)d_in[0];
    const float* h0  = (const float*)d_in[1];
    const float* c0  = (const float*)d_in[2];
    const float* wih = (const float*)d_in[3];
    const float* whh = (const float*)d_in[4];
    const float* bih = (const float*)d_in[5];
    const float* bhh = (const float*)d_in[6];
    float* out = (float*)d_out;

    const int smemA = 256 * 64 * 4;                              // 64 KB
    const int smemB = (16 * 512 * 4 + 4 * HH + 4 * G4) * 4;      // 141312 B
    cudaFuncSetAttribute(k_gatesx, cudaFuncAttributeMaxDynamicSharedMemorySize, smemA);
    cudaFuncSetAttribute(k_recur,  cudaFuncAttributeMaxDynamicSharedMemorySize, smemB);

    k_transpose<<<(NB * 32 * G4) / 512, 512>>>(whh);
    k_gatesx<<<NB * 16, 512, smemA>>>(x, wih, bih, bhh);
    k_recur<<<NB * 4, 512, smemB>>>(h0, c0, out);
}

// round 9
// speedup vs baseline: 1.1369x; 1.1369x over previous
#include <cuda_runtime.h>
#include <cstdint>

// Problem dims
#define BB 16          // batch
#define TT 256         // timesteps
#define NB 32          // LSTM blocks
#define II 64          // input per block
#define HH 128         // hidden per block
#define G4 512         // 4*H gate rows per block

// ---------------------------------------------------------------------------
// Packed fp32x2 FMA helpers (sm_100+): operands are register pairs; ulonglong2
// vector loads land in aligned pairs so no packing MOVs are required.
// ---------------------------------------------------------------------------
__device__ __forceinline__ void ffma2(unsigned long long& d,
                                      unsigned long long a,
                                      unsigned long long b) {
    asm("fma.rn.f32x2 %0, %1, %2, %0;" : "+l"(d) : "l"(a), "l"(b));
}
__device__ __forceinline__ float hadd2(unsigned long long v) {
    float lo, hi;
    asm("mov.b64 {%0, %1}, %2;" : "=f"(lo), "=f"(hi) : "l"(v));
    return lo + hi;
}

// ---------------------------------------------------------------------------
// Scratch (device globals: allocation-free per harness rules)
// ---------------------------------------------------------------------------
// gates_x[t][n][b][g]  (biases folded in):  256*32*16*512 floats = 268 MB
__device__ float g_gx[(size_t)TT * NB * BB * G4];
// transposed W_hh: [n][kc][g][4] with kc = k/4 (32 chunks): 8 MB
__device__ float g_wt4[(size_t)NB * (HH / 4) * G4 * 4];

// ---------------------------------------------------------------------------
// Kernel 0: transpose W_hh [n][g][k] -> [n][k/4][g][4]
// ---------------------------------------------------------------------------
__global__ void k_transpose(const float* __restrict__ whh) {
    int idx = blockIdx.x * blockDim.x + threadIdx.x;   // over NB*32*512
    int g  = idx & 511;
    int kc = (idx >> 9) & 31;
    int n  = idx >> 14;
    float4 v = *(const float4*)(whh + ((size_t)(n * G4 + g)) * HH + kc * 4);
    *(float4*)(g_wt4 + ((size_t)((n * 32 + kc) * G4 + g)) * 4) = v;
}

// ---------------------------------------------------------------------------
// Kernel A: gates_x[b,t,n,g] = sum_i x[b,t,n*64+i] * W_ih[n,g,i] + bi + bh
// Grid: 512 CTAs = (n) x (tc); 512 threads, thread = g. FFMA2 inner loop.
// ---------------------------------------------------------------------------
__global__ void __launch_bounds__(512, 1)
k_gatesx(const float* __restrict__ x,
         const float* __restrict__ wih,
         const float* __restrict__ bih,
         const float* __restrict__ bhh) {
    extern __shared__ float xs[];           // [256 rows][64] = 64 KB
    int n  = blockIdx.x & 31;
    int tc = blockIdx.x >> 5;               // 0..15 (16 timesteps each)
    int g  = threadIdx.x;

    // Register-resident weight row for this gate: 64 floats = 16 ulonglong2
    ulonglong2 w[16];
    const ulonglong2* wp = (const ulonglong2*)(wih + ((size_t)(n * G4 + g)) * II);
#pragma unroll
    for (int j = 0; j < 16; j++) w[j] = wp[j];
    float bias = bih[n * G4 + g] + bhh[n * G4 + g];

    // Stage 256 x-rows (16 t x 16 b), row r = b*16 + tl
    for (int idx = threadIdx.x; idx < 256 * 16; idx += 512) {
        int r  = idx >> 4;
        int i4 = idx & 15;
        int b  = r >> 4;
        int tl = r & 15;
        int t  = tc * 16 + tl;
        ((float4*)xs)[idx] =
            *(const float4*)(x + (size_t)(b * TT + t) * (NB * II) + n * II + i4 * 4);
    }
    __syncthreads();

    for (int r = 0; r < 256; r++) {
        const ulonglong2* xr = ((const ulonglong2*)xs) + r * 16;
        unsigned long long accA = 0ull, accB = 0ull;
#pragma unroll
        for (int j = 0; j < 16; j++) {
            ulonglong2 xv = xr[j];
            ffma2(accA, w[j].x, xv.x);
            ffma2(accB, w[j].y, xv.y);
        }
        float acc = bias + hadd2(accA) + hadd2(accB);
        int b  = r >> 4;
        int tl = r & 15;
        int t  = tc * 16 + tl;
        g_gx[((size_t)(t * NB + n) * BB + b) * G4 + g] = acc;
    }
}

// ---------------------------------------------------------------------------
// Kernel B: recurrence. Grid: 128 CTAs = (n x 4 batch-groups of 4 batches).
// 512 threads, thread = gate row g. Weights fully resident: kc 0..15 in
// REGISTERS (64 regs, loop-invariant), kc 16..31 in SMEM (128 KB). No L2
// weight streaming. FFMA2 gemv.
// ---------------------------------------------------------------------------
__global__ void __launch_bounds__(512, 1)
k_recur(const float* __restrict__ h0,
        const float* __restrict__ c0,
        float* __restrict__ out) {
    extern __shared__ float smem[];
    ulonglong2* ws8 = (ulonglong2*)smem;         // [16 kc][512 g] (kc 16..31)
    float*  hs  = smem + 16 * 512 * 4;           // [4][128] floats
    float*  gs  = hs + 4 * HH;                   // [4][512] floats

    int n  = blockIdx.x >> 2;
    int bg = blockIdx.x & 3;
    int b0 = bg * 4;
    int tid = threadIdx.x;
    int g = tid;

    const ulonglong2* wglob = (const ulonglong2*)(g_wt4 + (size_t)n * 32 * G4 * 4);

    // Register-resident weights: kc 0..15 (k = 0..63), invariant over t
    ulonglong2 wr[16];
#pragma unroll
    for (int j = 0; j < 16; j++) wr[j] = wglob[j * 512 + g];

    // SMEM-resident weights: kc 16..31
    for (int idx = tid; idx < 16 * 512; idx += 512)
        ws8[idx] = wglob[16 * 512 + idx];

    // Initial state
    int eb = tid >> 7;       // local batch 0..3
    int eh = tid & 127;      // hidden index
    float c_reg = c0[(b0 + eb) * (NB * HH) + n * HH + eh];
    hs[eb * HH + eh] = h0[(b0 + eb) * (NB * HH) + n * HH + eh];
    __syncthreads();

    const ulonglong2* h8 = (const ulonglong2*)hs;   // [b*32 + kc]

    for (int t = 0; t < TT; t++) {
        // gates_x for this step (issued early; consumed after the gemv)
        const float* gxp = g_gx + ((size_t)(t * NB + n) * BB + b0) * G4 + g;
        float gx0 = gxp[0];
        float gx1 = gxp[512];
        float gx2 = gxp[1024];
        float gx3 = gxp[1536];

        unsigned long long a0a = 0, a0b = 0, a1a = 0, a1b = 0,
                           a2a = 0, a2b = 0, a3a = 0, a3b = 0;

        // k = 0..63 from registers
#pragma unroll
        for (int kc = 0; kc < 16; kc++) {
            ulonglong2 w = wr[kc];
            ulonglong2 hv;
            hv = h8[kc];        ffma2(a0a, w.x, hv.x); ffma2(a0b, w.y, hv.y);
            hv = h8[32 + kc];   ffma2(a1a, w.x, hv.x); ffma2(a1b, w.y, hv.y);
            hv = h8[64 + kc];   ffma2(a2a, w.x, hv.x); ffma2(a2b, w.y, hv.y);
            hv = h8[96 + kc];   ffma2(a3a, w.x, hv.x); ffma2(a3b, w.y, hv.y);
        }
        // k = 64..127 from SMEM
#pragma unroll
        for (int kc = 0; kc < 16; kc++) {
            ulonglong2 w = ws8[kc * 512 + g];
            ulonglong2 hv;
            hv = h8[16 + kc];   ffma2(a0a, w.x, hv.x); ffma2(a0b, w.y, hv.y);
            hv = h8[48 + kc];   ffma2(a1a, w.x, hv.x); ffma2(a1b, w.y, hv.y);
            hv = h8[80 + kc];   ffma2(a2a, w.x, hv.x); ffma2(a2b, w.y, hv.y);
            hv = h8[112 + kc];  ffma2(a3a, w.x, hv.x); ffma2(a3b, w.y, hv.y);
        }

        gs[0 * 512 + g] = hadd2(a0a) + hadd2(a0b) + gx0;
        gs[1 * 512 + g] = hadd2(a1a) + hadd2(a1b) + gx1;
        gs[2 * 512 + g] = hadd2(a2a) + hadd2(a2b) + gx2;
        gs[3 * 512 + g] = hadd2(a3a) + hadd2(a3b) + gx3;
        __syncthreads();

        // Epilogue: gate activations + state update
        float gi = gs[eb * 512 + eh];
        float gf = gs[eb * 512 + 128 + eh];
        float gg = gs[eb * 512 + 256 + eh];
        float go = gs[eb * 512 + 384 + eh];

        float ig = 1.f / (1.f + __expf(-gi));
        float fg = 1.f / (1.f + __expf(-gf));
        float gt = 1.f - __fdividef(2.f, __expf(2.f * gg) + 1.f);
        float og = 1.f / (1.f + __expf(-go));

        c_reg = fg * c_reg + ig * gt;
        float ct = 1.f - __fdividef(2.f, __expf(2.f * c_reg) + 1.f);
        float hn = og * ct;

        hs[eb * HH + eh] = hn;
        out[((size_t)(b0 + eb) * TT + t) * (NB * HH) + n * HH + eh] = hn;
        __syncthreads();
    }

    // Final states: h_n then c_n appended after the [B,T,N*H] output
    size_t base = (size_t)BB * TT * NB * HH;
    out[base + (b0 + eb) * (NB * HH) + n * HH + eh] = hs[eb * HH + eh];
    out[base + (size_t)BB * NB * HH + (b0 + eb) * (NB * HH) + n * HH + eh] = c_reg;
}

// ---------------------------------------------------------------------------
// Launch
// ---------------------------------------------------------------------------
extern "C" void kernel_launch(void* const* d_in, const int* in_sizes, int n_in,
                              void* d_out, int out_size) {
    const float* x   = (const float*)d_in[0];
    const float* h0  = (const float*)d_in[1];
    const float* c0  = (const float*)d_in[2];
    const float* wih = (const float*)d_in[3];
    const float* whh = (const float*)d_in[4];
    const float* bih = (const float*)d_in[5];
    const float* bhh = (const float*)d_in[6];
    float* out = (float*)d_out;

    const int smemA = 256 * 64 * 4;                              // 64 KB
    const int smemB = 16 * 512 * 16 + 4 * HH * 4 + 4 * G4 * 4;   // 141312 B
    cudaFuncSetAttribute(k_gatesx, cudaFuncAttributeMaxDynamicSharedMemorySize, smemA);
    cudaFuncSetAttribute(k_recur,  cudaFuncAttributeMaxDynamicSharedMemorySize, smemB);

    k_transpose<<<(NB * 32 * G4) / 512, 512>>>(whh);
    k_gatesx<<<NB * 16, 512, smemA>>>(x, wih, bih, bhh);
    k_recur<<<NB * 4, 512, smemB>>>(h0, c0, out);
}